// round 11
// baseline (speedup 1.0000x reference)
#include <cuda_runtime.h>
#include <cstdint>

#define BN 1024
#define DN 256
#define LN 32

// Scratch (no allocations allowed)
__device__ int g_negcnt[LN];            // #rows with label != l
__device__ int g_neglist[LN * BN];      // stable-ordered negative row indices
__device__ int g_poscnt[LN];            // #anchors with label == l
__device__ int g_poslist[LN * BN];      // anchor row indices

// Write-through 128-bit store (st.global.wt): no dirty L2 allocation for the
// write-once output stream.
__device__ __forceinline__ void stwt4(float4* p, float4 v) {
    asm volatile("st.global.wt.v4.f32 [%0], {%1, %2, %3, %4};"
                 :: "l"(p), "f"(v.x), "f"(v.y), "f"(v.z), "f"(v.w) : "memory");
}

// ---------------------------------------------------------------------------
// Kernel 1: per-label lists + counts. One block per label, 1024 threads.
// Stable block-wide compaction via ballot/popc + warp-sum scan.
// Fires the PDL completion trigger so the gather grid launches ASAP.
// ---------------------------------------------------------------------------
__global__ void lists_kernel(const int* __restrict__ label) {
    int l = blockIdx.x;
    int t = threadIdx.x;
    int lane = t & 31;
    int wid  = t >> 5;
    __shared__ int wpre[32];
    __shared__ int s_total;

    bool neg = (label[t] != l);
    unsigned m = __ballot_sync(0xffffffffu, neg);
    int nrank = __popc(m & ((1u << lane) - 1u));
    if (lane == 0) wpre[wid] = __popc(m);
    __syncthreads();
    if (wid == 0) {
        int v = wpre[lane];
        int s = v;
        #pragma unroll
        for (int o = 1; o < 32; o <<= 1) {
            int n = __shfl_up_sync(0xffffffffu, s, o);
            if (lane >= o) s += n;
        }
        if (lane == 31) s_total = s;
        wpre[lane] = s - v;
    }
    __syncthreads();

    if (neg) {
        g_neglist[l * BN + wpre[wid] + nrank] = t;
    } else {
        int ppre  = (wid << 5) - wpre[wid];
        int prank = lane - nrank;
        g_poslist[l * BN + ppre + prank] = t;
    }
    if (t == 0) {
        g_negcnt[l] = s_total;
        g_poscnt[l] = BN - s_total;
    }
#if __CUDA_ARCH__ >= 900
    __syncthreads();
    cudaTriggerProgrammaticLaunchCompletion();   // release dependent grid early
#endif
}

// ---------------------------------------------------------------------------
// Threefry-2x32 (JAX partitionable scheme), key = (0, 42).
// bits(t) = out0 ^ out1 of threefry2x32(key, (hi=0, lo=t)).
// ---------------------------------------------------------------------------
__device__ __forceinline__ uint32_t rotl32(uint32_t x, int r) {
    return (x << r) | (x >> (32 - r));
}

__device__ __forceinline__ uint32_t threefry_bits32(uint32_t x0, uint32_t x1) {
    const uint32_t k0 = 0u, k1 = 42u;
    const uint32_t k2 = k0 ^ k1 ^ 0x1BD11BDAu;
    x0 += k0; x1 += k1;
#define TF_ROUND(r) { x0 += x1; x1 = rotl32(x1, (r)); x1 ^= x0; }
    TF_ROUND(13) TF_ROUND(15) TF_ROUND(26) TF_ROUND(6)
    x0 += k1; x1 += k2 + 1u;
    TF_ROUND(17) TF_ROUND(29) TF_ROUND(16) TF_ROUND(24)
    x0 += k2; x1 += k0 + 2u;
    TF_ROUND(13) TF_ROUND(15) TF_ROUND(26) TF_ROUND(6)
    x0 += k0; x1 += k1 + 3u;
    TF_ROUND(17) TF_ROUND(29) TF_ROUND(16) TF_ROUND(24)
    x0 += k1; x1 += k2 + 4u;
    TF_ROUND(13) TF_ROUND(15) TF_ROUND(26) TF_ROUND(6)
    x0 += k2; x1 += k0 + 5u;
#undef TF_ROUND
    return x0 ^ x1;
}

// ---------------------------------------------------------------------------
// Kernel 2: gather, two j-columns per block (R10 body), 512 threads =
// 2 warp-groups of 8 warps; each group runs the verified R5 loop for its own
// column (8 warps -> 8 different anchors concurrently). A/B change vs R10:
// __stcs -> st.global.wt on the output stream. PDL-gated on lists_kernel.
// ---------------------------------------------------------------------------
__global__ void gather_kernel(const float* __restrict__ embs,
                              float* __restrict__ out,
                              int max_count) {
#if __CUDA_ARCH__ >= 900
    cudaGridDependencySynchronize();
#endif
    int l  = blockIdx.y;
    int nc = g_negcnt[l];
    int pc = g_poscnt[l];
    if (pc == 0) return;

    int lane = threadIdx.x & 31;
    int wg   = threadIdx.x >> 8;          // warp-group 0 or 1
    int w    = (threadIdx.x >> 5) & 7;    // warp within group
    int j    = blockIdx.x * 2 + wg;       // this group's output column

    __shared__ float4 srow[2][DN / 4];    // 2 KB
    __shared__ int    spos[BN];           // anchor list (pc entries used)

    for (int t = threadIdx.x; t < pc; t += 512)
        spos[t] = g_poslist[l * BN + t];
    {
        int tt = threadIdx.x & 255;       // thread within group
        if (j < nc && tt < DN / 4) {
            int src = g_neglist[l * BN + j];
            srow[wg][tt] = ((const float4*)embs)[(size_t)src * (DN / 4) + tt];
        }
    }
    __syncthreads();

    if (j >= max_count) return;

    if (j < nc) {
        float4 v0 = srow[wg][lane];
        float4 v1 = srow[wg][lane + 32];
        for (int a = w; a < pc; a += 8) {
            int i = spos[a];
            float4* dst = (float4*)out + ((size_t)i * max_count + j) * (DN / 4);
            stwt4(dst + lane,      v0);
            stwt4(dst + lane + 32, v1);
        }
    } else {
        // padded tail: per-anchor uniform resample among the nc negatives
        for (int a = w; a < pc; a += 8) {
            int i = spos[a];
            int p = 0;
            if (lane == 0) {
                uint32_t t = (uint32_t)(i * max_count + j);   // row-major flat idx
                uint32_t bits = threefry_bits32(0u, t);
                float u = __uint_as_float((bits >> 9) | 0x3F800000u) - 1.0f;
                p = (int)__fmul_rn(u, (float)nc);             // trunc, matches XLA
                int cap = nc - 1;
                if (p > cap) p = cap;
            }
            p = __shfl_sync(0xffffffffu, p, 0);
            int src = g_neglist[l * BN + p];
            const float4* s = (const float4*)embs + (size_t)src * (DN / 4);
            float4*     dst = (float4*)out + ((size_t)i * max_count + j) * (DN / 4);
            stwt4(dst + lane,      s[lane]);
            stwt4(dst + lane + 32, s[lane + 32]);
        }
    }
}

// ---------------------------------------------------------------------------
extern "C" void kernel_launch(void* const* d_in, const int* in_sizes, int n_in,
                              void* d_out, int out_size) {
    const float* embs  = (const float*)d_in[0];
    const int*   label = (const int*)d_in[1];
    if (n_in >= 2 && in_sizes[0] == BN && in_sizes[1] == BN * DN) {
        embs  = (const float*)d_in[1];
        label = (const int*)d_in[0];
    }

    int max_count = out_size / (BN * DN);

    lists_kernel<<<LN, BN>>>(label);

    dim3 grid((max_count + 1) / 2, LN);

    // PDL launch: gather blocks spin up while lists_kernel drains; ordering
    // comes from the in-kernel cudaGridDependencySynchronize().
    cudaLaunchConfig_t cfg = {};
    cfg.gridDim  = grid;
    cfg.blockDim = dim3(512, 1, 1);
    cfg.dynamicSmemBytes = 0;
    cfg.stream = 0;
    cudaLaunchAttribute attr[1];
    attr[0].id = cudaLaunchAttributeProgrammaticStreamSerialization;
    attr[0].val.programmaticStreamSerializationAllowed = 1;
    cfg.attrs = attr;
    cfg.numAttrs = 1;

    cudaError_t err = cudaLaunchKernelEx(&cfg, gather_kernel,
                                         embs, (float*)d_out, max_count);
    if (err != cudaSuccess) {
        gather_kernel<<<grid, 512>>>(embs, (float*)d_out, max_count);
    }
}

// round 12
// speedup vs baseline: 1.0298x; 1.0298x over previous
#include <cuda_runtime.h>
#include <cstdint>

#define BN 1024
#define DN 256
#define LN 32

// Scratch (no allocations allowed)
__device__ int g_negcnt[LN];            // #rows with label != l
__device__ int g_neglist[LN * BN];      // stable-ordered negative row indices
__device__ int g_poscnt[LN];            // #anchors with label == l
__device__ int g_poslist[LN * BN];      // anchor row indices

// ---------------------------------------------------------------------------
// Kernel 1: per-label lists + counts. One block per label, 1024 threads.
// Stable block-wide compaction via ballot/popc + warp-sum scan.
// Fires the PDL completion trigger so the gather grid launches ASAP.
// ---------------------------------------------------------------------------
__global__ void lists_kernel(const int* __restrict__ label) {
    int l = blockIdx.x;
    int t = threadIdx.x;
    int lane = t & 31;
    int wid  = t >> 5;
    __shared__ int wpre[32];
    __shared__ int s_total;

    bool neg = (label[t] != l);
    unsigned m = __ballot_sync(0xffffffffu, neg);
    int nrank = __popc(m & ((1u << lane) - 1u));
    if (lane == 0) wpre[wid] = __popc(m);
    __syncthreads();
    if (wid == 0) {
        int v = wpre[lane];
        int s = v;
        #pragma unroll
        for (int o = 1; o < 32; o <<= 1) {
            int n = __shfl_up_sync(0xffffffffu, s, o);
            if (lane >= o) s += n;
        }
        if (lane == 31) s_total = s;
        wpre[lane] = s - v;
    }
    __syncthreads();

    if (neg) {
        g_neglist[l * BN + wpre[wid] + nrank] = t;
    } else {
        int ppre  = (wid << 5) - wpre[wid];
        int prank = lane - nrank;
        g_poslist[l * BN + ppre + prank] = t;
    }
    if (t == 0) {
        g_negcnt[l] = s_total;
        g_poscnt[l] = BN - s_total;
    }
#if __CUDA_ARCH__ >= 900
    __syncthreads();
    cudaTriggerProgrammaticLaunchCompletion();   // release dependent grid early
#endif
}

// ---------------------------------------------------------------------------
// Threefry-2x32 (JAX partitionable scheme), key = (0, 42).
// bits(t) = out0 ^ out1 of threefry2x32(key, (hi=0, lo=t)).
// ---------------------------------------------------------------------------
__device__ __forceinline__ uint32_t rotl32(uint32_t x, int r) {
    return (x << r) | (x >> (32 - r));
}

__device__ __forceinline__ uint32_t threefry_bits32(uint32_t x0, uint32_t x1) {
    const uint32_t k0 = 0u, k1 = 42u;
    const uint32_t k2 = k0 ^ k1 ^ 0x1BD11BDAu;
    x0 += k0; x1 += k1;
#define TF_ROUND(r) { x0 += x1; x1 = rotl32(x1, (r)); x1 ^= x0; }
    TF_ROUND(13) TF_ROUND(15) TF_ROUND(26) TF_ROUND(6)
    x0 += k1; x1 += k2 + 1u;
    TF_ROUND(17) TF_ROUND(29) TF_ROUND(16) TF_ROUND(24)
    x0 += k2; x1 += k0 + 2u;
    TF_ROUND(13) TF_ROUND(15) TF_ROUND(26) TF_ROUND(6)
    x0 += k0; x1 += k1 + 3u;
    TF_ROUND(17) TF_ROUND(29) TF_ROUND(16) TF_ROUND(24)
    x0 += k1; x1 += k2 + 4u;
    TF_ROUND(13) TF_ROUND(15) TF_ROUND(26) TF_ROUND(6)
    x0 += k2; x1 += k0 + 5u;
#undef TF_ROUND
    return x0 ^ x1;
}

// ---------------------------------------------------------------------------
// Kernel 2: gather, two j-columns per block, 512 threads = 2 warp-groups of
// 8 warps. Each group runs the verified R5 loop for its own column j (8 warps
// stride the anchor list -> 8 different anchors written concurrently).
// __stcs streaming stores (best measured policy). PDL-gated on lists_kernel.
// ---------------------------------------------------------------------------
__global__ void gather_kernel(const float* __restrict__ embs,
                              float* __restrict__ out,
                              int max_count) {
#if __CUDA_ARCH__ >= 900
    cudaGridDependencySynchronize();
#endif
    int l  = blockIdx.y;
    int nc = g_negcnt[l];
    int pc = g_poscnt[l];
    if (pc == 0) return;

    int lane = threadIdx.x & 31;
    int wg   = threadIdx.x >> 8;          // warp-group 0 or 1
    int w    = (threadIdx.x >> 5) & 7;    // warp within group
    int j    = blockIdx.x * 2 + wg;       // this group's output column

    __shared__ float4 srow[2][DN / 4];    // 2 KB
    __shared__ int    spos[BN];           // anchor list (pc entries used)

    for (int t = threadIdx.x; t < pc; t += 512)
        spos[t] = g_poslist[l * BN + t];
    {
        int tt = threadIdx.x & 255;       // thread within group
        if (j < nc && tt < DN / 4) {
            int src = g_neglist[l * BN + j];
            srow[wg][tt] = ((const float4*)embs)[(size_t)src * (DN / 4) + tt];
        }
    }
    __syncthreads();

    if (j >= max_count) return;

    if (j < nc) {
        float4 v0 = srow[wg][lane];
        float4 v1 = srow[wg][lane + 32];
        for (int a = w; a < pc; a += 8) {
            int i = spos[a];
            float4* dst = (float4*)out + ((size_t)i * max_count + j) * (DN / 4);
            __stcs(dst + lane,      v0);
            __stcs(dst + lane + 32, v1);
        }
    } else {
        // padded tail: per-anchor uniform resample among the nc negatives
        for (int a = w; a < pc; a += 8) {
            int i = spos[a];
            int p = 0;
            if (lane == 0) {
                uint32_t t = (uint32_t)(i * max_count + j);   // row-major flat idx
                uint32_t bits = threefry_bits32(0u, t);
                float u = __uint_as_float((bits >> 9) | 0x3F800000u) - 1.0f;
                p = (int)__fmul_rn(u, (float)nc);             // trunc, matches XLA
                int cap = nc - 1;
                if (p > cap) p = cap;
            }
            p = __shfl_sync(0xffffffffu, p, 0);
            int src = g_neglist[l * BN + p];
            const float4* s = (const float4*)embs + (size_t)src * (DN / 4);
            float4*     dst = (float4*)out + ((size_t)i * max_count + j) * (DN / 4);
            __stcs(dst + lane,      s[lane]);
            __stcs(dst + lane + 32, s[lane + 32]);
        }
    }
}

// ---------------------------------------------------------------------------
extern "C" void kernel_launch(void* const* d_in, const int* in_sizes, int n_in,
                              void* d_out, int out_size) {
    const float* embs  = (const float*)d_in[0];
    const int*   label = (const int*)d_in[1];
    if (n_in >= 2 && in_sizes[0] == BN && in_sizes[1] == BN * DN) {
        embs  = (const float*)d_in[1];
        label = (const int*)d_in[0];
    }

    int max_count = out_size / (BN * DN);

    lists_kernel<<<LN, BN>>>(label);

    dim3 grid((max_count + 1) / 2, LN);

    // PDL launch: gather blocks spin up while lists_kernel drains; ordering
    // comes from the in-kernel cudaGridDependencySynchronize().
    cudaLaunchConfig_t cfg = {};
    cfg.gridDim  = grid;
    cfg.blockDim = dim3(512, 1, 1);
    cfg.dynamicSmemBytes = 0;
    cfg.stream = 0;
    cudaLaunchAttribute attr[1];
    attr[0].id = cudaLaunchAttributeProgrammaticStreamSerialization;
    attr[0].val.programmaticStreamSerializationAllowed = 1;
    cfg.attrs = attr;
    cfg.numAttrs = 1;

    cudaError_t err = cudaLaunchKernelEx(&cfg, gather_kernel,
                                         embs, (float*)d_out, max_count);
    if (err != cudaSuccess) {
        gather_kernel<<<grid, 512>>>(embs, (float*)d_out, max_count);
    }
}

// round 13
// speedup vs baseline: 1.0422x; 1.0121x over previous
#include <cuda_runtime.h>
#include <cstdint>

#define BN 1024
#define DN 256
#define LN 32

// ---------------------------------------------------------------------------
// Threefry-2x32 (JAX partitionable scheme), key = (0, 42).
// bits(t) = out0 ^ out1 of threefry2x32(key, (hi=0, lo=t)).
// ---------------------------------------------------------------------------
__device__ __forceinline__ uint32_t rotl32(uint32_t x, int r) {
    return (x << r) | (x >> (32 - r));
}

__device__ __forceinline__ uint32_t threefry_bits32(uint32_t x0, uint32_t x1) {
    const uint32_t k0 = 0u, k1 = 42u;
    const uint32_t k2 = k0 ^ k1 ^ 0x1BD11BDAu;
    x0 += k0; x1 += k1;
#define TF_ROUND(r) { x0 += x1; x1 = rotl32(x1, (r)); x1 ^= x0; }
    TF_ROUND(13) TF_ROUND(15) TF_ROUND(26) TF_ROUND(6)
    x0 += k1; x1 += k2 + 1u;
    TF_ROUND(17) TF_ROUND(29) TF_ROUND(16) TF_ROUND(24)
    x0 += k2; x1 += k0 + 2u;
    TF_ROUND(13) TF_ROUND(15) TF_ROUND(26) TF_ROUND(6)
    x0 += k0; x1 += k1 + 3u;
    TF_ROUND(17) TF_ROUND(29) TF_ROUND(16) TF_ROUND(24)
    x0 += k1; x1 += k2 + 4u;
    TF_ROUND(13) TF_ROUND(15) TF_ROUND(26) TF_ROUND(6)
    x0 += k2; x1 += k0 + 5u;
#undef TF_ROUND
    return x0 ^ x1;
}

// ---------------------------------------------------------------------------
// Single fused kernel. Each block redundantly builds the (stable) negative /
// anchor lists for its label l IN SHARED MEMORY — no cross-block state, no
// fences, no second launch. Then runs the verified R10/R12 gather body:
// two j-columns per block, 512 threads = 2 warp-groups of 8 warps, each group
// striding the anchor list (8 different anchors written concurrently),
// __stcs streaming stores.
// ---------------------------------------------------------------------------
__global__ void fused_gather_kernel(const float* __restrict__ embs,
                                    const int* __restrict__ label,
                                    float* __restrict__ out,
                                    int max_count) {
    int l   = blockIdx.y;
    int tid = threadIdx.x;            // 0..511
    int lane = tid & 31;
    int wid  = tid >> 5;              // 0..15

    __shared__ int sneg[BN];          // stable-ordered negatives (4 KB)
    __shared__ int spos[BN];          // anchors (4 KB)
    __shared__ int wpre[16];          // per-warp exclusive neg prefixes
    __shared__ int s_nc;
    __shared__ float4 srow[2][DN / 4];   // 2 KB

    // --- block-local stable compaction: thread tid owns rows 2*tid, 2*tid+1 ---
    int2 lb = ((const int2*)label)[tid];
    int m0 = (lb.x != l);
    int m1 = (lb.y != l);
    int cnt = m0 + m1;

    int s = cnt;                      // warp-inclusive scan of neg counts
    #pragma unroll
    for (int o = 1; o < 32; o <<= 1) {
        int n = __shfl_up_sync(0xffffffffu, s, o);
        if (lane >= o) s += n;
    }
    if (lane == 31) wpre[wid] = s;    // warp totals (temporarily)
    __syncthreads();
    if (wid == 0 && lane < 16) {      // scan 16 warp totals in warp 0
        int v = wpre[lane];
        int t2 = v;
        #pragma unroll
        for (int o = 1; o < 16; o <<= 1) {
            int n = __shfl_up_sync(0x0000ffffu, t2, o);
            if (lane >= o) t2 += n;
        }
        wpre[lane] = t2 - v;          // exclusive prefix
        if (lane == 15) s_nc = t2;    // total negatives
    }
    __syncthreads();

    {
        int negbase = wpre[wid] + (s - cnt);   // exclusive neg rank of row 2*tid
        int rowbase = 2 * tid;
        int posbase = rowbase - negbase;
        int nb = negbase, pb = posbase;
        if (m0) sneg[nb++] = rowbase;     else spos[pb++] = rowbase;
        if (m1) sneg[nb]   = rowbase + 1; else spos[pb]   = rowbase + 1;
    }
    __syncthreads();

    int nc = s_nc;
    int pc = BN - nc;
    if (pc == 0) return;

    // --- gather body (R10/R12, verified) ---
    int wg = tid >> 8;                // warp-group 0 or 1
    int w  = (tid >> 5) & 7;          // warp within group
    int j  = blockIdx.x * 2 + wg;     // this group's output column

    {
        int tt = tid & 255;           // thread within group
        if (j < nc && tt < DN / 4) {
            int src = sneg[j];
            srow[wg][tt] = ((const float4*)embs)[(size_t)src * (DN / 4) + tt];
        }
    }
    __syncthreads();

    if (j >= max_count) return;

    if (j < nc) {
        float4 v0 = srow[wg][lane];
        float4 v1 = srow[wg][lane + 32];
        for (int a = w; a < pc; a += 8) {
            int i = spos[a];
            float4* dst = (float4*)out + ((size_t)i * max_count + j) * (DN / 4);
            __stcs(dst + lane,      v0);
            __stcs(dst + lane + 32, v1);
        }
    } else {
        // padded tail: per-anchor uniform resample among the nc negatives
        for (int a = w; a < pc; a += 8) {
            int i = spos[a];
            int p = 0;
            if (lane == 0) {
                uint32_t t = (uint32_t)(i * max_count + j);   // row-major flat idx
                uint32_t bits = threefry_bits32(0u, t);
                float u = __uint_as_float((bits >> 9) | 0x3F800000u) - 1.0f;
                p = (int)__fmul_rn(u, (float)nc);             // trunc, matches XLA
                int cap = nc - 1;
                if (p > cap) p = cap;
            }
            p = __shfl_sync(0xffffffffu, p, 0);
            int src = sneg[p];
            const float4* sp = (const float4*)embs + (size_t)src * (DN / 4);
            float4*      dst = (float4*)out + ((size_t)i * max_count + j) * (DN / 4);
            __stcs(dst + lane,      sp[lane]);
            __stcs(dst + lane + 32, sp[lane + 32]);
        }
    }
}

// ---------------------------------------------------------------------------
extern "C" void kernel_launch(void* const* d_in, const int* in_sizes, int n_in,
                              void* d_out, int out_size) {
    const float* embs  = (const float*)d_in[0];
    const int*   label = (const int*)d_in[1];
    if (n_in >= 2 && in_sizes[0] == BN && in_sizes[1] == BN * DN) {
        embs  = (const float*)d_in[1];
        label = (const int*)d_in[0];
    }

    int max_count = out_size / (BN * DN);

    dim3 grid((max_count + 1) / 2, LN);
    fused_gather_kernel<<<grid, 512>>>(embs, label, (float*)d_out, max_count);
}